// round 1
// baseline (speedup 1.0000x reference)
#include <cuda_runtime.h>
#include <math.h>

#define NSIDE 4096
#define KDIM  1024
#define NNTOT (4096ULL*4096ULL)
#define RC_CONST (1.0f/4096.0f)
#define OT_EPS_F 1e-6f

// ---------------- scratch (no allocations allowed) ----------------
__device__ float  g_P0[4096*4096];     // 64 MB
__device__ float  g_rnA[NSIDE];
__device__ float  g_rnB[NSIDE];
__device__ float  g_rowmax[NSIDE];
__device__ float  g_u[NSIDE];
__device__ float  g_v[NSIDE];
__device__ float  g_t[NSIDE];
__device__ double g_sumM, g_sumM2, g_sumP2, g_trace;
__device__ float  g_mu, g_invsig;
__device__ int    g_done;
__device__ unsigned g_maxdev;

// ---------------- init (must reset ALL state every replay) ----------------
__global__ void init_kernel() {
    int j = blockIdx.x * blockDim.x + threadIdx.x;
    if (j < NSIDE) { g_u[j] = 1.f; g_v[j] = 1.f; g_t[j] = 0.f; }
    if (j == 0) {
        g_sumM = 0.0; g_sumM2 = 0.0; g_sumP2 = 0.0; g_trace = 0.0;
        g_done = 0; g_maxdev = 0u;
    }
}

// ---------------- row inverse norms of ft / fs ----------------
__global__ void rownorm_kernel(const float* __restrict__ ft,
                               const float* __restrict__ fs) {
    int r = blockIdx.x;               // 0..8191
    const float* src = (r < NSIDE) ? (ft + (size_t)r * KDIM)
                                   : (fs + (size_t)(r - NSIDE) * KDIM);
    float4 v = ((const float4*)src)[threadIdx.x];   // 256 thr * 4 = 1024
    float s = v.x*v.x + v.y*v.y + v.z*v.z + v.w*v.w;
    #pragma unroll
    for (int o = 16; o > 0; o >>= 1) s += __shfl_down_sync(0xffffffffu, s, o);
    __shared__ float ws[8];
    if ((threadIdx.x & 31) == 0) ws[threadIdx.x >> 5] = s;
    __syncthreads();
    if (threadIdx.x == 0) {
        float t = 0.f;
        #pragma unroll
        for (int w = 0; w < 8; w++) t += ws[w];
        float inv = 1.f / fmaxf(sqrtf(t), 1e-12f);
        if (r < NSIDE) g_rnA[r] = inv; else g_rnB[r - NSIDE] = inv;
    }
}

// ---------------- SGEMM: Mraw = (ft . fs^T) scaled by inv norms ----------------
// 128x128 block tile, 8x8 per-thread frag, BK=16, register prefetch pipeline.
#define SSTR 132
__global__ __launch_bounds__(256)
void sgemm_kernel(const float* __restrict__ A, const float* __restrict__ B,
                  float* __restrict__ Mout) {
    __shared__ float As[16][SSTR];
    __shared__ float Bs[16][SSTR];
    int tid = threadIdx.x;
    int bm = blockIdx.y * 128, bn = blockIdx.x * 128;
    int tx = tid & 15, ty = tid >> 4;
    int lrow = tid >> 2;            // 0..63
    int lk   = (tid & 3) << 2;      // 0,4,8,12
    const float* Ap = A + (size_t)(bm + lrow) * KDIM + lk;
    const float* Bp = B + (size_t)(bn + lrow) * KDIM + lk;

    float acc[8][8];
    #pragma unroll
    for (int i = 0; i < 8; i++)
        #pragma unroll
        for (int j = 0; j < 8; j++) acc[i][j] = 0.f;

    // prefetch first tile
    float4 a0 = *(const float4*)Ap;
    float4 a1 = *(const float4*)(Ap + 64 * KDIM);
    float4 b0 = *(const float4*)Bp;
    float4 b1 = *(const float4*)(Bp + 64 * KDIM);
    Ap += 16; Bp += 16;

    for (int k0 = 0; k0 < KDIM; k0 += 16) {
        __syncthreads();
        As[lk+0][lrow]    = a0.x; As[lk+1][lrow]    = a0.y;
        As[lk+2][lrow]    = a0.z; As[lk+3][lrow]    = a0.w;
        As[lk+0][lrow+64] = a1.x; As[lk+1][lrow+64] = a1.y;
        As[lk+2][lrow+64] = a1.z; As[lk+3][lrow+64] = a1.w;
        Bs[lk+0][lrow]    = b0.x; Bs[lk+1][lrow]    = b0.y;
        Bs[lk+2][lrow]    = b0.z; Bs[lk+3][lrow]    = b0.w;
        Bs[lk+0][lrow+64] = b1.x; Bs[lk+1][lrow+64] = b1.y;
        Bs[lk+2][lrow+64] = b1.z; Bs[lk+3][lrow+64] = b1.w;
        __syncthreads();
        if (k0 + 16 < KDIM) {   // prefetch next tile, overlap with compute
            a0 = *(const float4*)Ap;
            a1 = *(const float4*)(Ap + 64 * KDIM);
            b0 = *(const float4*)Bp;
            b1 = *(const float4*)(Bp + 64 * KDIM);
            Ap += 16; Bp += 16;
        }
        #pragma unroll
        for (int kk = 0; kk < 16; kk++) {
            float ar[8], br[8];
            *(float4*)&ar[0] = *(const float4*)&As[kk][ty*8];
            *(float4*)&ar[4] = *(const float4*)&As[kk][ty*8+4];
            *(float4*)&br[0] = *(const float4*)&Bs[kk][tx*8];
            *(float4*)&br[4] = *(const float4*)&Bs[kk][tx*8+4];
            #pragma unroll
            for (int i = 0; i < 8; i++)
                #pragma unroll
                for (int j = 0; j < 8; j++)
                    acc[i][j] = fmaf(ar[i], br[j], acc[i][j]);
        }
    }

    // epilogue: scale by inverse norms, write raw M, accumulate sum/sumsq
    float ra[8], rb[8];
    #pragma unroll
    for (int i = 0; i < 8; i++) ra[i] = g_rnA[bm + ty*8 + i];
    #pragma unroll
    for (int j = 0; j < 8; j++) rb[j] = g_rnB[bn + tx*8 + j];
    float s = 0.f, s2 = 0.f;
    #pragma unroll
    for (int i = 0; i < 8; i++) {
        float* orow = Mout + (size_t)(bm + ty*8 + i) * NSIDE + bn + tx*8;
        #pragma unroll
        for (int j = 0; j < 8; j++) {
            float m = acc[i][j] * ra[i] * rb[j];
            orow[j] = m;
            s += m; s2 = fmaf(m, m, s2);
        }
    }
    #pragma unroll
    for (int o = 16; o > 0; o >>= 1) {
        s  += __shfl_down_sync(0xffffffffu, s,  o);
        s2 += __shfl_down_sync(0xffffffffu, s2, o);
    }
    __shared__ float ws[8], ws2[8];
    if ((tid & 31) == 0) { ws[tid >> 5] = s; ws2[tid >> 5] = s2; }
    __syncthreads();
    if (tid == 0) {
        double S = 0.0, S2 = 0.0;
        for (int w = 0; w < 8; w++) { S += ws[w]; S2 += ws2[w]; }
        atomicAdd(&g_sumM, S); atomicAdd(&g_sumM2, S2);
    }
}

// ---------------- stats finalize ----------------
__global__ void stats_kernel() {
    double mu  = g_sumM / (double)NNTOT;
    double var = (g_sumM2 - (double)NNTOT * mu * mu) / ((double)NNTOT - 1.0);
    g_mu = (float)mu;
    g_invsig = (float)(1.0 / sqrt(var));
}

// ---------------- per-row max of raw M ----------------
__global__ void rowmax_kernel(const float* __restrict__ M) {
    int r = blockIdx.x;
    const float* row = M + (size_t)r * NSIDE;
    float m = -INFINITY;
    for (int j = threadIdx.x; j < NSIDE; j += 256) m = fmaxf(m, row[j]);
    #pragma unroll
    for (int o = 16; o > 0; o >>= 1) m = fmaxf(m, __shfl_down_sync(0xffffffffu, m, o));
    __shared__ float ws[8];
    if ((threadIdx.x & 31) == 0) ws[threadIdx.x >> 5] = m;
    __syncthreads();
    if (threadIdx.x == 0) {
        float t = ws[0];
        #pragma unroll
        for (int w = 1; w < 8; w++) t = fmaxf(t, ws[w]);
        g_rowmax[r] = t;
    }
}

// ---------------- M -> standardized M' (in place) and P0 ----------------
__global__ void pass2_kernel(float* __restrict__ M) {
    size_t idx = (size_t)blockIdx.x * 256 + threadIdx.x;
    int row = (int)(idx >> 12);
    float m = M[idx];
    float invs = g_invsig;
    M[idx] = (m - g_mu) * invs;
    g_P0[idx] = expf((m - g_rowmax[row]) * invs);
}

// ---------------- Sinkhorn: row pass  s_i = sum_j P0_ij v_j ; u_i = scale/s_i
__global__ void rowpass_kernel(float scale, int check) {
    if (check && g_done) return;
    int i = blockIdx.x;
    if (threadIdx.x == 0) g_t[i] = 0.f;   // prep for colpass accumulation
    const float4* row = (const float4*)(g_P0 + (size_t)i * NSIDE);
    const float4* v4  = (const float4*)g_v;
    float acc = 0.f;
    #pragma unroll 4
    for (int j = threadIdx.x; j < NSIDE / 4; j += 128) {
        float4 p = row[j]; float4 vv = v4[j];
        acc += p.x*vv.x + p.y*vv.y + p.z*vv.z + p.w*vv.w;
    }
    #pragma unroll
    for (int o = 16; o > 0; o >>= 1) acc += __shfl_down_sync(0xffffffffu, acc, o);
    __shared__ float ws[4];
    if ((threadIdx.x & 31) == 0) ws[threadIdx.x >> 5] = acc;
    __syncthreads();
    if (threadIdx.x == 0)
        g_u[i] = scale / (ws[0] + ws[1] + ws[2] + ws[3]);
}

// ---------------- Sinkhorn: col pass  t_j = sum_i P0_ij u_i (atomic gather)
__global__ void colpass_kernel(int check) {
    if (check && g_done) return;
    float acc[16];
    #pragma unroll
    for (int c = 0; c < 16; c++) acc[c] = 0.f;
    int i0 = blockIdx.x * 16;
    for (int rr = 0; rr < 16; rr++) {
        float ui = g_u[i0 + rr];
        const float* row = g_P0 + (size_t)(i0 + rr) * NSIDE + threadIdx.x;
        #pragma unroll
        for (int c = 0; c < 16; c++)
            acc[c] = fmaf(ui, row[c * 256], acc[c]);
    }
    #pragma unroll
    for (int c = 0; c < 16; c++)
        atomicAdd(&g_t[threadIdx.x + c * 256], acc[c]);
}

// ---------------- Sinkhorn: convergence check + decide + v update ----------------
__global__ void check_kernel() {
    if (g_done) return;
    int j = blockIdx.x * 256 + threadIdx.x;
    float dev = fabsf(g_v[j] * g_t[j] - RC_CONST);
    atomicMax(&g_maxdev, __float_as_uint(dev));   // dev >= 0: uint order valid
}
__global__ void decide_kernel() {
    if (!g_done && __uint_as_float(g_maxdev) <= OT_EPS_F) g_done = 1;
    g_maxdev = 0u;
}
__global__ void vupdate_kernel(float scale, int check) {
    if (check && g_done) return;
    int j = blockIdx.x * 256 + threadIdx.x;
    g_v[j] = scale / g_t[j];
}

// ---------------- materialize P, accumulate ||P||^2 and trace ----------------
__global__ void materialize_kernel(float* __restrict__ Pout) {
    size_t idx = (size_t)blockIdx.x * 256 + threadIdx.x;
    int row = (int)(idx >> 12), col = (int)(idx & 4095);
    float p = g_u[row] * g_P0[idx] * g_v[col];
    Pout[idx] = p;
    float s2 = p * p;
    float tr = (row == col) ? p : 0.f;
    #pragma unroll
    for (int o = 16; o > 0; o >>= 1) {
        s2 += __shfl_down_sync(0xffffffffu, s2, o);
        tr += __shfl_down_sync(0xffffffffu, tr, o);
    }
    __shared__ float ws[8], wt[8];
    if ((threadIdx.x & 31) == 0) { ws[threadIdx.x >> 5] = s2; wt[threadIdx.x >> 5] = tr; }
    __syncthreads();
    if (threadIdx.x == 0) {
        double S = 0.0, T = 0.0;
        for (int w = 0; w < 8; w++) { S += ws[w]; T += wt[w]; }
        atomicAdd(&g_sumP2, S);
        if (T != 0.0) atomicAdd(&g_trace, T);
    }
}

__global__ void loss_kernel(float* __restrict__ out0) {
    out0[0] = (float)sqrt(g_sumP2 - 2.0 * g_trace + 4096.0);
}

// ---------------- launch ----------------
extern "C" void kernel_launch(void* const* d_in, const int* in_sizes, int n_in,
                              void* d_out, int out_size) {
    const float* ft = (const float*)d_in[0];
    const float* fs = (const float*)d_in[1];
    float* out  = (float*)d_out;
    float* Pout = out + 1;
    float* Mout = out + 1 + (size_t)NNTOT;

    init_kernel<<<16, 256>>>();
    rownorm_kernel<<<2 * NSIDE, 256>>>(ft, fs);

    dim3 gemm_grid(32, 32);
    sgemm_kernel<<<gemm_grid, 256>>>(ft, fs, Mout);
    stats_kernel<<<1, 1>>>();
    rowmax_kernel<<<NSIDE, 256>>>(Mout);
    pass2_kernel<<<65536, 256>>>(Mout);

    for (int it = 0; it < 20; it++) {
        rowpass_kernel<<<NSIDE, 128>>>(RC_CONST, 1);
        colpass_kernel<<<256, 256>>>(1);
        check_kernel<<<16, 256>>>();
        decide_kernel<<<1, 1>>>();
        vupdate_kernel<<<16, 256>>>(RC_CONST, 1);
    }

    // final row-normalize then col-normalize (unconditional)
    rowpass_kernel<<<NSIDE, 128>>>(1.0f, 0);
    colpass_kernel<<<256, 256>>>(0);
    vupdate_kernel<<<16, 256>>>(1.0f, 0);

    materialize_kernel<<<65536, 256>>>(Pout);
    loss_kernel<<<1, 1>>>(out);
}

// round 5
// speedup vs baseline: 1.5328x; 1.5328x over previous
#include <cuda_runtime.h>
#include <cuda_bf16.h>
#include <math.h>
#include <stdint.h>

#define NSIDE 4096
#define KDIM  1024
#define K3    3072
#define NCHUNK 48
#define NNTOT (4096ULL*4096ULL)
#define RC_CONST (1.0f/4096.0f)
#define OT_EPS_F 1e-6f

#define STAGES 4
#define STAGE_BYTES 32768   // 16KB A + 16KB B per stage (BK=64 bf16 = 128B rows)
#define GEMM_SMEM (STAGES*STAGE_BYTES + 1024)

// ---------------- scratch (no allocations allowed) ----------------
__device__ float  g_P0[4096*4096];              // 64 MB
__device__ __align__(16) float g_M[4096*4096];  // 64 MB aligned GEMM output
__device__ __align__(16) __nv_bfloat16 g_A2[4096*3072];  // 24 MB [hi | lo | hi]
__device__ __align__(16) __nv_bfloat16 g_B2[4096*3072];  // 24 MB [hi | hi | lo]
__device__ float  g_rnA[NSIDE];
__device__ float  g_rnB[NSIDE];
__device__ float  g_rowmax[NSIDE];
__device__ float  g_u[NSIDE];
__device__ float  g_v[NSIDE];
__device__ float  g_t[NSIDE];
__device__ double g_sumM, g_sumM2, g_sumP2, g_trace;
__device__ float  g_mu, g_invsig;
__device__ int    g_done;

static __device__ __forceinline__ uint32_t smem_u32(const void* p) {
    uint32_t a;
    asm("{ .reg .u64 t; cvta.to.shared.u64 t, %1; cvt.u32.u64 %0, t; }"
        : "=r"(a) : "l"(p));
    return a;
}
#define SWZ(o) ((o) ^ (((o) >> 3) & 0x70))

// ---------------- init ----------------
__global__ void init_kernel() {
    int j = blockIdx.x * blockDim.x + threadIdx.x;
    if (j < NSIDE) { g_u[j] = 1.f; g_v[j] = 1.f; g_t[j] = 0.f; }
    if (j == 0) {
        g_sumM = 0.0; g_sumM2 = 0.0; g_sumP2 = 0.0; g_trace = 0.0;
        g_done = 0;
    }
}

// ---------------- row inverse norms ----------------
__global__ void rownorm_kernel(const float* __restrict__ ft,
                               const float* __restrict__ fs) {
    int r = blockIdx.x;               // 0..8191
    const float* src = (r < NSIDE) ? (ft + (size_t)r * KDIM)
                                   : (fs + (size_t)(r - NSIDE) * KDIM);
    float4 v = ((const float4*)src)[threadIdx.x];
    float s = v.x*v.x + v.y*v.y + v.z*v.z + v.w*v.w;
    #pragma unroll
    for (int o = 16; o > 0; o >>= 1) s += __shfl_down_sync(0xffffffffu, s, o);
    __shared__ float ws[8];
    if ((threadIdx.x & 31) == 0) ws[threadIdx.x >> 5] = s;
    __syncthreads();
    if (threadIdx.x == 0) {
        float t = 0.f;
        #pragma unroll
        for (int w = 0; w < 8; w++) t += ws[w];
        float inv = 1.f / fmaxf(sqrtf(t), 1e-12f);
        if (r < NSIDE) g_rnA[r] = inv; else g_rnB[r - NSIDE] = inv;
    }
}

// ---------------- split fp32 -> 3-term bf16, K-concatenated ----------------
// A2 row: [hiA | loA | hiA]   B2 row: [hiB | hiB | loB]
// GEMM over K=3072 yields hiA.hiB + loA.hiB + hiA.loB  (loA.loB dropped, ~2^-16)
__global__ void split_kernel(const float* __restrict__ ft,
                             const float* __restrict__ fs) {
    size_t idx = (size_t)blockIdx.x * 256 + threadIdx.x;   // float4 index
    const float* src; __nv_bfloat16* dst; int isA;
    size_t i = idx;
    if (i < (1ULL << 20)) { src = ft; dst = g_A2; isA = 1; }
    else                  { src = fs; dst = g_B2; isA = 0; i -= (1ULL << 20); }
    float4 v = ((const float4*)src)[i];
    size_t row = i >> 8;            // 256 float4 per 1024-float row
    size_t c   = (i & 255) * 4;
    float f[4] = {v.x, v.y, v.z, v.w};
    unsigned short hs[4], ls[4];
    #pragma unroll
    for (int j = 0; j < 4; j++) {
        __nv_bfloat16 h = __float2bfloat16(f[j]);
        float hf = __bfloat162float(h);
        __nv_bfloat16 l = __float2bfloat16(f[j] - hf);
        hs[j] = *(unsigned short*)&h;
        ls[j] = *(unsigned short*)&l;
    }
    __nv_bfloat16* base = dst + row * K3 + c;
    if (isA) {
        *(uint2*)(base)        = *(uint2*)hs;   // seg0: hi
        *(uint2*)(base + 1024) = *(uint2*)ls;   // seg1: lo
        *(uint2*)(base + 2048) = *(uint2*)hs;   // seg2: hi
    } else {
        *(uint2*)(base)        = *(uint2*)hs;   // seg0: hi
        *(uint2*)(base + 1024) = *(uint2*)hs;   // seg1: hi
        *(uint2*)(base + 2048) = *(uint2*)ls;   // seg2: lo
    }
}

// ---------------- HMMA bf16 GEMM via mma.sync ----------------
// g_M[i][j] = (ft_i . fs_j) * rnA_i * rnB_j, fp32 accumulation on tensor cores.
// CTA tile 128x128, 8 warps (2 M x 4 N), warp tile 64x32, BK=64, 4-stage cp.async.

static __device__ __forceinline__ void load_stage_async(int tid, int bm, int bn,
                                                        char* tb, int stage, int kc) {
    const __nv_bfloat16* Ap = g_A2 + (size_t)bm * K3 + kc * 64;
    const __nv_bfloat16* Bp = g_B2 + (size_t)bn * K3 + kc * 64;
    char* As = tb + stage * STAGE_BYTES;
    char* Bs = As + 16384;
    #pragma unroll
    for (int r = 0; r < 4; r++) {
        int id = tid + r * 256; int row = id >> 3, c16 = id & 7;
        uint32_t off = SWZ(row * 128 + c16 * 16);
        uint32_t sa = smem_u32(As + off);
        uint32_t sb = smem_u32(Bs + off);
        const void* ga = Ap + (size_t)row * K3 + c16 * 8;
        const void* gb = Bp + (size_t)row * K3 + c16 * 8;
        asm volatile("cp.async.cg.shared.global [%0], [%1], 16;" :: "r"(sa), "l"(ga));
        asm volatile("cp.async.cg.shared.global [%0], [%1], 16;" :: "r"(sb), "l"(gb));
    }
    asm volatile("cp.async.commit_group;" ::: "memory");
}

static __device__ __forceinline__ void compute_chunk(uint32_t Abase, uint32_t Bbase,
                                                     int wm, int wn, int lane,
                                                     float acc[4][4][4]) {
    int arow = wm * 64 + (lane & 15);
    int brow = wn * 32 + (lane & 15);
    int chalf = (lane >> 4) * 16;
    #pragma unroll
    for (int k16 = 0; k16 < 4; k16++) {
        uint32_t a[4][4], b[2][4];
        #pragma unroll
        for (int mi = 0; mi < 4; mi++) {
            uint32_t off = SWZ((arow + mi * 16) * 128 + k16 * 32 + chalf);
            asm volatile("ldmatrix.sync.aligned.m8n8.x4.shared.b16 {%0,%1,%2,%3}, [%4];"
                : "=r"(a[mi][0]), "=r"(a[mi][1]), "=r"(a[mi][2]), "=r"(a[mi][3])
                : "r"(Abase + off));
        }
        #pragma unroll
        for (int bj = 0; bj < 2; bj++) {
            uint32_t off = SWZ((brow + bj * 16) * 128 + k16 * 32 + chalf);
            asm volatile("ldmatrix.sync.aligned.m8n8.x4.shared.b16 {%0,%1,%2,%3}, [%4];"
                : "=r"(b[bj][0]), "=r"(b[bj][1]), "=r"(b[bj][2]), "=r"(b[bj][3])
                : "r"(Bbase + off));
        }
        #pragma unroll
        for (int mi = 0; mi < 4; mi++)
            #pragma unroll
            for (int nj = 0; nj < 4; nj++) {
                uint32_t b0 = (nj & 1) ? b[nj >> 1][1] : b[nj >> 1][0];
                uint32_t b1 = (nj & 1) ? b[nj >> 1][3] : b[nj >> 1][2];
                asm volatile(
                    "mma.sync.aligned.m16n8k16.row.col.f32.bf16.bf16.f32 "
                    "{%0,%1,%2,%3}, {%4,%5,%6,%7}, {%8,%9}, {%0,%1,%2,%3};"
                    : "+f"(acc[mi][nj][0]), "+f"(acc[mi][nj][1]),
                      "+f"(acc[mi][nj][2]), "+f"(acc[mi][nj][3])
                    : "r"(a[mi][0]), "r"(a[mi][1]), "r"(a[mi][2]), "r"(a[mi][3]),
                      "r"(b0), "r"(b1));
            }
    }
}

__global__ __launch_bounds__(256)
void mma_gemm_kernel() {
    extern __shared__ char dsm[];
    char* tb = (char*)(((uintptr_t)dsm + 1023) & ~(uintptr_t)1023);
    int tid = threadIdx.x, lane = tid & 31, wid = tid >> 5;
    int wm = wid >> 2, wn = wid & 3;
    int bm = blockIdx.y * 128, bn = blockIdx.x * 128;

    float acc[4][4][4];
    #pragma unroll
    for (int i = 0; i < 4; i++)
        #pragma unroll
        for (int j = 0; j < 4; j++)
            #pragma unroll
            for (int k = 0; k < 4; k++) acc[i][j][k] = 0.f;

    // prologue: stages 0..2
    #pragma unroll
    for (int s = 0; s < STAGES - 1; s++)
        load_stage_async(tid, bm, bn, tb, s, s);

    uint32_t sbase = smem_u32(tb);
    for (int c = 0; c < NCHUNK; c++) {
        asm volatile("cp.async.wait_group %0;" :: "n"(STAGES - 2) : "memory");
        __syncthreads();
        if (c + STAGES - 1 < NCHUNK)
            load_stage_async(tid, bm, bn, tb, (c + STAGES - 1) & (STAGES - 1), c + STAGES - 1);
        uint32_t Ab = sbase + (c & (STAGES - 1)) * STAGE_BYTES;
        compute_chunk(Ab, Ab + 16384, wm, wn, lane, acc);
    }

    // epilogue: scale, write g_M (aligned), accumulate stats
    int lrow = lane >> 2;
    int lcol2 = (lane & 3) * 2;
    float ssum = 0.f, ssum2 = 0.f;
    #pragma unroll
    for (int mi = 0; mi < 4; mi++) {
        int gr0 = bm + wm * 64 + mi * 16 + lrow;
        float ra0 = g_rnA[gr0], ra1 = g_rnA[gr0 + 8];
        float* o0 = g_M + (size_t)gr0 * NSIDE + bn + wn * 32;
        float* o1 = o0 + 8 * NSIDE;
        #pragma unroll
        for (int nj = 0; nj < 4; nj++) {
            int gc = bn + wn * 32 + nj * 8 + lcol2;
            float rb0 = g_rnB[gc], rb1 = g_rnB[gc + 1];
            float2 v0 = make_float2(acc[mi][nj][0] * ra0 * rb0,
                                    acc[mi][nj][1] * ra0 * rb1);
            float2 v1 = make_float2(acc[mi][nj][2] * ra1 * rb0,
                                    acc[mi][nj][3] * ra1 * rb1);
            *(float2*)(o0 + nj * 8 + lcol2) = v0;
            *(float2*)(o1 + nj * 8 + lcol2) = v1;
            ssum += v0.x + v0.y + v1.x + v1.y;
            ssum2 = fmaf(v0.x, v0.x, fmaf(v0.y, v0.y,
                     fmaf(v1.x, v1.x, fmaf(v1.y, v1.y, ssum2))));
        }
    }
    #pragma unroll
    for (int o = 16; o > 0; o >>= 1) {
        ssum  += __shfl_down_sync(0xffffffffu, ssum,  o);
        ssum2 += __shfl_down_sync(0xffffffffu, ssum2, o);
    }
    __shared__ float wsum[8], wsum2[8];
    if (lane == 0) { wsum[wid] = ssum; wsum2[wid] = ssum2; }
    __syncthreads();
    if (tid == 0) {
        double S = 0.0, S2 = 0.0;
        #pragma unroll
        for (int w = 0; w < 8; w++) { S += wsum[w]; S2 += wsum2[w]; }
        atomicAdd(&g_sumM, S); atomicAdd(&g_sumM2, S2);
    }
}

// ---------------- stats finalize ----------------
__global__ void stats_kernel() {
    double mu  = g_sumM / (double)NNTOT;
    double var = (g_sumM2 - (double)NNTOT * mu * mu) / ((double)NNTOT - 1.0);
    g_mu = (float)mu;
    g_invsig = (float)(1.0 / sqrt(var));
}

// ---------------- per-row max of raw M (vectorized over g_M) ----------------
__global__ void rowmax_kernel() {
    int r = blockIdx.x;
    const float4* row = (const float4*)(g_M + (size_t)r * NSIDE);
    float m = -INFINITY;
    for (int j = threadIdx.x; j < NSIDE / 4; j += 256) {
        float4 v = row[j];
        m = fmaxf(m, fmaxf(fmaxf(v.x, v.y), fmaxf(v.z, v.w)));
    }
    #pragma unroll
    for (int o = 16; o > 0; o >>= 1) m = fmaxf(m, __shfl_down_sync(0xffffffffu, m, o));
    __shared__ float ws[8];
    if ((threadIdx.x & 31) == 0) ws[threadIdx.x >> 5] = m;
    __syncthreads();
    if (threadIdx.x == 0) {
        float t = ws[0];
        #pragma unroll
        for (int w = 1; w < 8; w++) t = fmaxf(t, ws[w]);
        g_rowmax[r] = t;
    }
}

// ---------------- g_M -> standardized M' (to Mout, unaligned) and P0 ----------------
__global__ void pass2_kernel(float* __restrict__ Mout) {
    size_t idx = (size_t)blockIdx.x * 256 + threadIdx.x;
    int row = (int)(idx >> 12);
    float m = g_M[idx];
    float invs = g_invsig;
    Mout[idx] = (m - g_mu) * invs;       // scalar store: Mout only 4B aligned
    g_P0[idx] = expf((m - g_rowmax[row]) * invs);
}

// ---------------- Sinkhorn row pass ----------------
__global__ void rowpass_kernel(float scale, int check) {
    if (check && g_done) return;
    int i = blockIdx.x;
    if (threadIdx.x == 0) g_t[i] = 0.f;
    const float4* row = (const float4*)(g_P0 + (size_t)i * NSIDE);
    const float4* v4  = (const float4*)g_v;
    float acc = 0.f;
    #pragma unroll 4
    for (int j = threadIdx.x; j < NSIDE / 4; j += 128) {
        float4 p = row[j]; float4 vv = v4[j];
        acc += p.x*vv.x + p.y*vv.y + p.z*vv.z + p.w*vv.w;
    }
    #pragma unroll
    for (int o = 16; o > 0; o >>= 1) acc += __shfl_down_sync(0xffffffffu, acc, o);
    __shared__ float ws[4];
    if ((threadIdx.x & 31) == 0) ws[threadIdx.x >> 5] = acc;
    __syncthreads();
    if (threadIdx.x == 0)
        g_u[i] = scale / (ws[0] + ws[1] + ws[2] + ws[3]);
}

// ---------------- Sinkhorn col pass ----------------
__global__ void colpass_kernel(int check) {
    if (check && g_done) return;
    float acc[16];
    #pragma unroll
    for (int c = 0; c < 16; c++) acc[c] = 0.f;
    int i0 = blockIdx.x * 16;
    for (int rr = 0; rr < 16; rr++) {
        float ui = g_u[i0 + rr];
        const float* row = g_P0 + (size_t)(i0 + rr) * NSIDE + threadIdx.x;
        #pragma unroll
        for (int c = 0; c < 16; c++)
            acc[c] = fmaf(ui, row[c * 256], acc[c]);
    }
    #pragma unroll
    for (int c = 0; c < 16; c++)
        atomicAdd(&g_t[threadIdx.x + c * 256], acc[c]);
}

// ---------------- convergence check + decide (fused, one block) ----------------
__global__ void checkdecide_kernel() {
    if (g_done) return;
    float dev = 0.f;
    #pragma unroll
    for (int r = 0; r < 4; r++) {
        int j = threadIdx.x + r * 1024;
        dev = fmaxf(dev, fabsf(g_v[j] * g_t[j] - RC_CONST));
    }
    #pragma unroll
    for (int o = 16; o > 0; o >>= 1)
        dev = fmaxf(dev, __shfl_down_sync(0xffffffffu, dev, o));
    __shared__ float ws[32];
    if ((threadIdx.x & 31) == 0) ws[threadIdx.x >> 5] = dev;
    __syncthreads();
    if (threadIdx.x == 0) {
        float m = ws[0];
        #pragma unroll
        for (int w = 1; w < 32; w++) m = fmaxf(m, ws[w]);
        if (m <= OT_EPS_F) g_done = 1;
    }
}

__global__ void vupdate_kernel(float scale, int check) {
    if (check && g_done) return;
    int j = blockIdx.x * 256 + threadIdx.x;
    g_v[j] = scale / g_t[j];
}

// ---------------- materialize P + loss pieces ----------------
__global__ void materialize_kernel(float* __restrict__ Pout) {
    size_t idx = (size_t)blockIdx.x * 256 + threadIdx.x;
    int row = (int)(idx >> 12), col = (int)(idx & 4095);
    float p = g_u[row] * g_P0[idx] * g_v[col];
    Pout[idx] = p;
    float s2 = p * p;
    float tr = (row == col) ? p : 0.f;
    #pragma unroll
    for (int o = 16; o > 0; o >>= 1) {
        s2 += __shfl_down_sync(0xffffffffu, s2, o);
        tr += __shfl_down_sync(0xffffffffu, tr, o);
    }
    __shared__ float ws[8], wt[8];
    if ((threadIdx.x & 31) == 0) { ws[threadIdx.x >> 5] = s2; wt[threadIdx.x >> 5] = tr; }
    __syncthreads();
    if (threadIdx.x == 0) {
        double S = 0.0, T = 0.0;
        for (int w = 0; w < 8; w++) { S += ws[w]; T += wt[w]; }
        atomicAdd(&g_sumP2, S);
        if (T != 0.0) atomicAdd(&g_trace, T);
    }
}

__global__ void loss_kernel(float* __restrict__ out0) {
    out0[0] = (float)sqrt(g_sumP2 - 2.0 * g_trace + 4096.0);
}

// ---------------- launch ----------------
extern "C" void kernel_launch(void* const* d_in, const int* in_sizes, int n_in,
                              void* d_out, int out_size) {
    const float* ft = (const float*)d_in[0];
    const float* fs = (const float*)d_in[1];
    float* out  = (float*)d_out;
    float* Pout = out + 1;
    float* Mout = out + 1 + (size_t)NNTOT;

    cudaFuncSetAttribute(mma_gemm_kernel,
                         cudaFuncAttributeMaxDynamicSharedMemorySize, GEMM_SMEM);

    init_kernel<<<16, 256>>>();
    rownorm_kernel<<<2 * NSIDE, 256>>>(ft, fs);
    split_kernel<<<8192, 256>>>(ft, fs);

    dim3 gemm_grid(32, 32);
    mma_gemm_kernel<<<gemm_grid, 256, GEMM_SMEM>>>();

    stats_kernel<<<1, 1>>>();
    rowmax_kernel<<<NSIDE, 256>>>();
    pass2_kernel<<<65536, 256>>>(Mout);

    for (int it = 0; it < 20; it++) {
        rowpass_kernel<<<NSIDE, 128>>>(RC_CONST, 1);
        colpass_kernel<<<256, 256>>>(1);
        checkdecide_kernel<<<1, 1024>>>();
        vupdate_kernel<<<16, 256>>>(RC_CONST, 1);
    }

    rowpass_kernel<<<NSIDE, 128>>>(1.0f, 0);
    colpass_kernel<<<256, 256>>>(0);
    vupdate_kernel<<<16, 256>>>(1.0f, 0);

    materialize_kernel<<<65536, 256>>>(Pout);
    loss_kernel<<<1, 1>>>(out);
}